// round 7
// baseline (speedup 1.0000x reference)
#include <cuda_runtime.h>
#include <cuda_bf16.h>
#include <stdint.h>

// ---------------- problem constants ----------------
#define BB     4
#define CCH    256          // FIN
#define HH     64
#define WWDIM  64
#define SS     4096         // H*W
#define MP     (BB*SS)      // 16384 positions
#define NMEM   64
#define SQG    16
#define QKROWS 2048         // 1024 q rows + 1024 k rows
#define CINR   258          // FIN + 2 pos channels
#define KPAD   288          // CINR padded to multiple of 32

// ---------------- scratch (device globals; no allocation) ----------------
__device__ __nv_bfloat16 g_A[(size_t)MP * KPAD];          // xp^T, position-major, bf16, K padded
__device__ __nv_bfloat16 g_W[(size_t)QKROWS * KPAD];      // [wq; wk] bf16, K padded
__device__ __nv_bfloat16 g_QK[(size_t)MP * QKROWS];       // q,k per position (bf16)
__device__ float         g_attn[(size_t)MP * NMEM];       // attn_mean per position
__device__ float         g_Wv[NMEM * CCH];                // v @ wout^T  (fused tail)

// ---------------- prep: transpose x into g_A (cols 0..255) ----------------
__global__ void prep_x_kernel(const float* __restrict__ x) {
    __shared__ float tile[32][33];
    int b  = blockIdx.z;
    int c0 = blockIdx.x * 32;
    int s0 = blockIdx.y * 32;
    int tx = threadIdx.x, ty = threadIdx.y;  // 32 x 8
    const float* xb = x + (size_t)b * CCH * SS;
#pragma unroll
    for (int i = 0; i < 4; i++) {
        int c = c0 + ty + i * 8;
        tile[ty + i * 8][tx] = xb[(size_t)c * SS + s0 + tx];
    }
    __syncthreads();
#pragma unroll
    for (int i = 0; i < 4; i++) {
        int s = s0 + ty + i * 8;
        int p = b * SS + s;
        g_A[(size_t)p * KPAD + c0 + tx] = __float2bfloat16(tile[tx][ty + i * 8]);
    }
}

// ---------------- prep: pos channels + zero pad (cols 256..287) ----------------
__global__ void prep_pos_kernel(const float* __restrict__ pos) {
    int g = blockIdx.x * blockDim.x + threadIdx.x;   // MP*32 threads
    int p = g >> 5, cc = g & 31;
    int s = p & (SS - 1);
    float v = 0.f;
    if (cc == 0)      v = pos[s];           // gy
    else if (cc == 1) v = pos[SS + s];      // gx
    g_A[(size_t)p * KPAD + 256 + cc] = __float2bfloat16(v);
}

// ---------------- prep: weights [wq; wk] -> bf16 padded ----------------
__global__ void prep_w_kernel(const float* __restrict__ wq, const float* __restrict__ wk) {
    int g = blockIdx.x * blockDim.x + threadIdx.x;   // QKROWS*KPAD threads
    int r = g / KPAD, c = g % KPAD;
    float v = 0.f;
    if (c < CINR) v = (r < 1024) ? wq[r * CINR + c] : wk[(r - 1024) * CINR + c];
    g_W[g] = __float2bfloat16(v);
}

// ---------------- prep: Wv[m][o] = sum_f v[m][f] * wout[o][f] ----------------
__global__ void prep_wv_kernel(const float* __restrict__ v, const float* __restrict__ wout) {
    __shared__ float vs[CCH];
    int m = blockIdx.x, o = threadIdx.x;   // 64 blocks x 256 threads
    vs[o] = v[m * CCH + o];
    __syncthreads();
    const float4* wrow = reinterpret_cast<const float4*>(wout + (size_t)o * CCH);
    float acc = 0.f;
#pragma unroll 8
    for (int f4 = 0; f4 < CCH / 4; f4++) {
        float4 w = wrow[f4];
        acc += vs[f4 * 4 + 0] * w.x + vs[f4 * 4 + 1] * w.y +
               vs[f4 * 4 + 2] * w.z + vs[f4 * 4 + 3] * w.w;
    }
    g_Wv[m * CCH + o] = acc;
}

// ---------------- bf16 mma.sync helper ----------------
__device__ __forceinline__ void mma16816(float* c, const unsigned* a, const unsigned* b) {
    asm volatile(
        "mma.sync.aligned.m16n8k16.row.col.f32.bf16.bf16.f32 "
        "{%0,%1,%2,%3}, {%4,%5,%6,%7}, {%8,%9}, {%0,%1,%2,%3};\n"
        : "+f"(c[0]), "+f"(c[1]), "+f"(c[2]), "+f"(c[3])
        : "r"(a[0]), "r"(a[1]), "r"(a[2]), "r"(a[3]), "r"(b[0]), "r"(b[1]));
}

// ---------------- cp.async 16B helper ----------------
__device__ __forceinline__ void cp16(void* smem, const void* gmem) {
    unsigned saddr = (unsigned)__cvta_generic_to_shared(smem);
    asm volatile("cp.async.cg.shared.global [%0], [%1], 16;\n" :: "r"(saddr), "l"(gmem));
}
__device__ __forceinline__ void cp_commit() {
    asm volatile("cp.async.commit_group;\n" ::: "memory");
}
template <int N>
__device__ __forceinline__ void cp_wait() {
    asm volatile("cp.async.wait_group %0;\n" :: "n"(N) : "memory");
}

// ---------------- GEMM: g_QK[p][n] = sum_k g_A[p][k] * g_W[n][k] ----------------
// 128x128x32 block tile, 2x4 warp grid (64x32 warp tiles), cp.async double buffer.
#define GBM 128
#define GBN 128
#define GBK 32
#define GPITCH 40   // bf16 elements per smem row (conflict-free fragment loads)
#define KTILES (KPAD / GBK)   // 9

__global__ __launch_bounds__(256) void gemm_qk_kernel() {
    __shared__ __align__(16) __nv_bfloat16 As[2][GBM * GPITCH];
    __shared__ __align__(16) __nv_bfloat16 Bs[2][GBN * GPITCH];
    int tid  = threadIdx.x;
    int warp = tid >> 5, lane = tid & 31;
    int wm = warp & 1, wn = warp >> 1;      // warp grid 2(m) x 4(n)
    int gr = lane >> 2, tg = lane & 3;
    int m0 = blockIdx.x * GBM;
    int n0 = blockIdx.y * GBN;

    // staging coordinates for this thread (2 x 16B per operand per tile)
    int r0 = tid >> 2,        c0 = (tid & 3) * 8;          // vv = tid
    int r1 = (tid + 256) >> 2, c1 = ((tid + 256) & 3) * 8; // vv = tid + 256

    float acc[4][4][4];
#pragma unroll
    for (int i = 0; i < 4; i++)
#pragma unroll
        for (int j = 0; j < 4; j++)
#pragma unroll
            for (int q = 0; q < 4; q++) acc[i][j][q] = 0.f;

    // prefetch tile 0 into buffer 0
    {
        int k0 = 0;
        cp16(&As[0][r0 * GPITCH + c0], &g_A[(size_t)(m0 + r0) * KPAD + k0 + c0]);
        cp16(&Bs[0][r0 * GPITCH + c0], &g_W[(size_t)(n0 + r0) * KPAD + k0 + c0]);
        cp16(&As[0][r1 * GPITCH + c1], &g_A[(size_t)(m0 + r1) * KPAD + k0 + c1]);
        cp16(&Bs[0][r1 * GPITCH + c1], &g_W[(size_t)(n0 + r1) * KPAD + k0 + c1]);
        cp_commit();
    }

    for (int kt = 0; kt < KTILES; kt++) {
        int cur = kt & 1;
        if (kt + 1 < KTILES) {
            int nb = (kt + 1) & 1;
            int k0 = (kt + 1) * GBK;
            cp16(&As[nb][r0 * GPITCH + c0], &g_A[(size_t)(m0 + r0) * KPAD + k0 + c0]);
            cp16(&Bs[nb][r0 * GPITCH + c0], &g_W[(size_t)(n0 + r0) * KPAD + k0 + c0]);
            cp16(&As[nb][r1 * GPITCH + c1], &g_A[(size_t)(m0 + r1) * KPAD + k0 + c1]);
            cp16(&Bs[nb][r1 * GPITCH + c1], &g_W[(size_t)(n0 + r1) * KPAD + k0 + c1]);
            cp_commit();
            cp_wait<1>();   // current tile's group done; next still in flight
        } else {
            cp_wait<0>();
        }
        __syncthreads();

#pragma unroll
        for (int ks = 0; ks < GBK; ks += 16) {
            unsigned a[4][4];
#pragma unroll
            for (int mf = 0; mf < 4; mf++) {
                const __nv_bfloat16* pA = &As[cur][(wm * 64 + mf * 16 + gr) * GPITCH + ks + tg * 2];
                a[mf][0] = *reinterpret_cast<const unsigned*>(pA);
                a[mf][1] = *reinterpret_cast<const unsigned*>(pA + 8 * GPITCH);
                a[mf][2] = *reinterpret_cast<const unsigned*>(pA + 8);
                a[mf][3] = *reinterpret_cast<const unsigned*>(pA + 8 * GPITCH + 8);
            }
            unsigned bf[4][2];
#pragma unroll
            for (int nf = 0; nf < 4; nf++) {
                const __nv_bfloat16* pB = &Bs[cur][(wn * 32 + nf * 8 + gr) * GPITCH + ks + tg * 2];
                bf[nf][0] = *reinterpret_cast<const unsigned*>(pB);
                bf[nf][1] = *reinterpret_cast<const unsigned*>(pB + 8);
            }
#pragma unroll
            for (int mf = 0; mf < 4; mf++)
#pragma unroll
                for (int nf = 0; nf < 4; nf++)
                    mma16816(acc[mf][nf], a[mf], bf[nf]);
        }
        __syncthreads();   // protect buffer `cur` from next-next prefetch
    }

    // epilogue -> bf16
#pragma unroll
    for (int mf = 0; mf < 4; mf++) {
#pragma unroll
        for (int nf = 0; nf < 4; nf++) {
            int row = m0 + wm * 64 + mf * 16 + gr;
            int col = n0 + wn * 32 + nf * 8 + tg * 2;
            float* c = acc[mf][nf];
            *reinterpret_cast<__nv_bfloat162*>(&g_QK[(size_t)row * QKROWS + col]) =
                __floats2bfloat162_rn(c[0], c[1]);
            *reinterpret_cast<__nv_bfloat162*>(&g_QK[(size_t)(row + 8) * QKROWS + col]) =
                __floats2bfloat162_rn(c[2], c[3]);
        }
    }
}

// ---------------- attention: normalize groups, mean over slots, attn ----------------
// warp per position; lane handles memory slots m = lane and lane+32
__global__ __launch_bounds__(256) void attn_kernel(const float* __restrict__ bq,
                                                   const float* __restrict__ bk) {
    int warp = threadIdx.x >> 5, lane = threadIdx.x & 31;
    int p = blockIdx.x * 8 + warp;
    const __nv_bfloat16* qk = g_QK + (size_t)p * QKROWS;

    float qs[SQG];
#pragma unroll
    for (int j = 0; j < SQG; j++) qs[j] = 0.f;

#pragma unroll
    for (int mi = 0; mi < 2; mi++) {
        int m = lane + mi * 32;
        float qv[SQG], ss = 0.f;
#pragma unroll
        for (int j = 0; j < SQG; j++) {
            float q = __bfloat162float(qk[m * SQG + j]) + bq[m * SQG + j];
            qv[j] = q; ss += q * q;
        }
        float inv = 1.f / fmaxf(sqrtf(ss), 1e-12f);
#pragma unroll
        for (int j = 0; j < SQG; j++) qs[j] += qv[j] * inv;
    }
    // reduce qs over all 32 lanes (=> sum over all 64 memory slots)
#pragma unroll
    for (int off = 16; off > 0; off >>= 1)
#pragma unroll
        for (int j = 0; j < SQG; j++)
            qs[j] += __shfl_xor_sync(0xffffffffu, qs[j], off);

#pragma unroll
    for (int mi = 0; mi < 2; mi++) {
        int m = lane + mi * 32;
        float ss = 0.f, dot = 0.f;
#pragma unroll
        for (int j = 0; j < SQG; j++) {
            float kvv = __bfloat162float(qk[1024 + m * SQG + j]) + bk[m * SQG + j];
            ss += kvv * kvv; dot += qs[j] * kvv;
        }
        float inv = 1.f / fmaxf(sqrtf(ss), 1e-12f);
        g_attn[(size_t)p * NMEM + m] = dot * inv * (1.f / 64.f);
    }
}

// ---------------- output: out = x + attn @ Wv + bout, written [B,256,H,W] ----------------
__global__ __launch_bounds__(256) void out_kernel(const float* __restrict__ x,
                                                  const float* __restrict__ bout,
                                                  float* __restrict__ out) {
    __shared__ float attn_s[64][65];
    __shared__ __align__(16) float wv_s[64][32];
    int p0 = blockIdx.x * 64;
    int o0 = blockIdx.y * 32;
    int tid = threadIdx.x;
    int px = tid & 63, oq = tid >> 6;   // oq in 0..3, 8 outputs each (contiguous)

    // load attn tile [64 pos][64 m]
#pragma unroll
    for (int i = 0; i < 16; i++) {
        int idx = tid + i * 256;
        int pr = idx >> 6, mm = idx & 63;
        attn_s[pr][mm] = g_attn[(size_t)(p0 + pr) * NMEM + mm];
    }
    // load Wv slice [64 m][32 o]
#pragma unroll
    for (int i = 0; i < 8; i++) {
        int idx = tid + i * 256;
        int mm = idx >> 5, oo = idx & 31;
        wv_s[mm][oo] = g_Wv[mm * CCH + o0 + oo];
    }
    __syncthreads();

    float acc[8];
#pragma unroll
    for (int i = 0; i < 8; i++) acc[i] = 0.f;

#pragma unroll 4
    for (int m = 0; m < 64; m++) {
        float a = attn_s[px][m];
        float4 w0 = *reinterpret_cast<const float4*>(&wv_s[m][oq * 8]);
        float4 w1 = *reinterpret_cast<const float4*>(&wv_s[m][oq * 8 + 4]);
        acc[0] += a * w0.x; acc[1] += a * w0.y; acc[2] += a * w0.z; acc[3] += a * w0.w;
        acc[4] += a * w1.x; acc[5] += a * w1.y; acc[6] += a * w1.z; acc[7] += a * w1.w;
    }

    int p = p0 + px;
    int b = p >> 12, s = p & (SS - 1);
#pragma unroll
    for (int i = 0; i < 8; i++) {
        int o = o0 + oq * 8 + i;
        size_t gi = ((size_t)b * CCH + o) * SS + s;
        out[gi] = x[gi] + acc[i] + bout[o];
    }
}

// ---------------- launch ----------------
extern "C" void kernel_launch(void* const* d_in, const int* in_sizes, int n_in,
                              void* d_out, int out_size) {
    const float* x    = (const float*)d_in[0];
    const float* pos  = (const float*)d_in[1];
    const float* wq   = (const float*)d_in[2];
    const float* bq   = (const float*)d_in[3];
    const float* wk   = (const float*)d_in[4];
    const float* bk   = (const float*)d_in[5];
    const float* v    = (const float*)d_in[6];
    const float* wout = (const float*)d_in[7];
    const float* bout = (const float*)d_in[8];
    float* out = (float*)d_out;

    prep_x_kernel<<<dim3(CCH / 32, SS / 32, BB), dim3(32, 8)>>>(x);
    prep_pos_kernel<<<(MP * 32) / 256, 256>>>(pos);
    prep_w_kernel<<<(QKROWS * KPAD) / 256, 256>>>(wq, wk);
    prep_wv_kernel<<<NMEM, 256>>>(v, wout);
    gemm_qk_kernel<<<dim3(MP / GBM, QKROWS / GBN), 256>>>();
    attn_kernel<<<MP / 8, 256>>>(bq, bk);
    out_kernel<<<dim3(MP / 64, CCH / 32), 256>>>(x, bout, out);
}

// round 10
// speedup vs baseline: 1.5628x; 1.5628x over previous
#include <cuda_runtime.h>
#include <cuda_bf16.h>
#include <stdint.h>

// ---------------- problem constants ----------------
#define BB     4
#define CCH    256          // FIN
#define SS     4096         // H*W
#define MP     (BB*SS)      // 16384 positions
#define NMEM   64
#define SQG    16
#define QKROWS 2048         // 1024 q rows + 1024 k rows
#define CINR   258          // FIN + 2 pos channels
#define KPAD   320          // CINR padded to 5 x 64
#define NKT    5            // K tiles of 64

// ---------------- scratch (device globals; no allocation) ----------------
__device__ __nv_bfloat16 g_A[(size_t)MP * KPAD];          // xp^T bf16, K padded
__device__ __nv_bfloat16 g_W[(size_t)QKROWS * KPAD];      // [wq; wk] bf16, K padded
__device__ __nv_bfloat16 g_QK[(size_t)MP * QKROWS];       // q,k per position (bf16)
__device__ float         g_attn[(size_t)MP * NMEM];       // attn_mean per position
__device__ float         g_Wv[NMEM * CCH];                // v @ wout^T (fused tail)

// ---------------- PTX helpers (base sm_103 only; NO tcgen05) ----------------
__device__ __forceinline__ uint32_t smem_u32(const void* p) {
    uint32_t a;
    asm("{ .reg .u64 t; cvta.to.shared.u64 t, %1; cvt.u32.u64 %0, t; }" : "=r"(a) : "l"(p));
    return a;
}
__device__ __forceinline__ void cp16(uint32_t saddr, const void* g) {
    asm volatile("cp.async.cg.shared.global [%0], [%1], 16;\n" :: "r"(saddr), "l"(g));
}
__device__ __forceinline__ void cp_commit() {
    asm volatile("cp.async.commit_group;\n" ::: "memory");
}
template <int N> __device__ __forceinline__ void cp_wait() {
    asm volatile("cp.async.wait_group %0;\n" :: "n"(N) : "memory");
}
__device__ __forceinline__ void mma16816(float* c, const unsigned* a, const unsigned* b) {
    asm volatile(
        "mma.sync.aligned.m16n8k16.row.col.f32.bf16.bf16.f32 "
        "{%0,%1,%2,%3}, {%4,%5,%6,%7}, {%8,%9}, {%0,%1,%2,%3};\n"
        : "+f"(c[0]), "+f"(c[1]), "+f"(c[2]), "+f"(c[3])
        : "r"(a[0]), "r"(a[1]), "r"(a[2]), "r"(a[3]), "r"(b[0]), "r"(b[1]));
}
__device__ __forceinline__ void ldsm_x4(unsigned& r0, unsigned& r1, unsigned& r2,
                                        unsigned& r3, uint32_t a) {
    asm volatile("ldmatrix.sync.aligned.m8n8.x4.shared.b16 {%0,%1,%2,%3}, [%4];"
                 : "=r"(r0), "=r"(r1), "=r"(r2), "=r"(r3) : "r"(a));
}
// SW128 swizzle for 128-byte rows: chunk ^= (row & 7)
__device__ __forceinline__ uint32_t swz(uint32_t off) { return off ^ ((off >> 3) & 0x70); }

// ---------------- prep: transpose x into g_A (cols 0..255) ----------------
__global__ void prep_x_kernel(const float* __restrict__ x) {
    __shared__ float tile[32][33];
    int b  = blockIdx.z;
    int c0 = blockIdx.x * 32;
    int s0 = blockIdx.y * 32;
    int tx = threadIdx.x, ty = threadIdx.y;  // 32 x 8
    const float* xb = x + (size_t)b * CCH * SS;
#pragma unroll
    for (int i = 0; i < 4; i++) {
        int c = c0 + ty + i * 8;
        tile[ty + i * 8][tx] = xb[(size_t)c * SS + s0 + tx];
    }
    __syncthreads();
#pragma unroll
    for (int i = 0; i < 4; i++) {
        int s = s0 + ty + i * 8;
        int p = b * SS + s;
        g_A[(size_t)p * KPAD + c0 + tx] = __float2bfloat16(tile[tx][ty + i * 8]);
    }
}

// ---------------- prep: pos channels + zero pad (cols 256..319) ----------------
__global__ void prep_pos_kernel(const float* __restrict__ pos) {
    int g = blockIdx.x * blockDim.x + threadIdx.x;   // MP*64 threads
    int p = g >> 6, cc = g & 63;
    int s = p & (SS - 1);
    float v = 0.f;
    if (cc == 0)      v = pos[s];
    else if (cc == 1) v = pos[SS + s];
    g_A[(size_t)p * KPAD + 256 + cc] = __float2bfloat16(v);
}

// ---------------- prep: weights [wq; wk] -> bf16 padded ----------------
__global__ void prep_w_kernel(const float* __restrict__ wq, const float* __restrict__ wk) {
    int g = blockIdx.x * blockDim.x + threadIdx.x;   // QKROWS*KPAD threads
    int r = g / KPAD, c = g % KPAD;
    float v = 0.f;
    if (c < CINR) v = (r < 1024) ? wq[r * CINR + c] : wk[(r - 1024) * CINR + c];
    g_W[g] = __float2bfloat16(v);
}

// ---------------- prep: Wv[m][o] = sum_f v[m][f] * wout[o][f] ----------------
// grid (NMEM, 4); block 256 = 64 o-lanes x 4 f-quarters; smem reduce, no atomics.
__global__ __launch_bounds__(256) void prep_wv_kernel(const float* __restrict__ v,
                                                      const float* __restrict__ wout) {
    __shared__ float vs[CCH];
    __shared__ float part[256];
    int m  = blockIdx.x;
    int oc = blockIdx.y;          // chunk of 64 outputs
    int tid = threadIdx.x;
    int ol = tid & 63, fq = tid >> 6;
    vs[tid] = v[m * CCH + tid];
    __syncthreads();
    int o = oc * 64 + ol;
    const float4* wr = reinterpret_cast<const float4*>(wout + (size_t)o * CCH + fq * 64);
    float acc = 0.f;
#pragma unroll
    for (int i = 0; i < 16; i++) {
        float4 w = wr[i];
        int f = fq * 64 + i * 4;
        acc += vs[f] * w.x + vs[f + 1] * w.y + vs[f + 2] * w.z + vs[f + 3] * w.w;
    }
    part[tid] = acc;
    __syncthreads();
    if (fq == 0)
        g_Wv[m * CCH + o] = part[ol] + part[ol + 64] + part[ol + 128] + part[ol + 192];
}

// ---------------- GEMM: g_QK[p][n] = sum_k g_A[p][k] * g_W[n][k] ----------------
// 128x128x64 block tile, 2x4 warp grid (64x32 warp tiles), cp.async double buffer,
// SW128-swizzled smem, ldmatrix.x4 fragment loads.
#define GBM 128
#define GBN 128
#define TBK 64
#define STAGE_A   16384                 // bytes per A tile (128 x 128B)
#define SM_AOFF(s) ((s) * STAGE_A)      // A0 @0, A1 @16KB
#define SM_BOFF(s) (32768 + (s) * STAGE_A)
#define SM_TOTAL   65536

__device__ __forceinline__ void stage_tile(uint32_t sbase, uint32_t aoff, uint32_t boff,
                                           int m0, int n0, int kt, int tid) {
    int kk = kt * TBK;
#pragma unroll
    for (int i = 0; i < 4; i++) {       // 128 rows x 8 x 16B each for A and B
        int idx = tid + i * 256;
        int row = idx >> 3, ch = idx & 7;
        uint32_t so = swz(row * 128 + ch * 16);
        cp16(sbase + aoff + so, &g_A[(size_t)(m0 + row) * KPAD + kk + ch * 8]);
        cp16(sbase + boff + so, &g_W[(size_t)(n0 + row) * KPAD + kk + ch * 8]);
    }
    cp_commit();
}

__global__ __launch_bounds__(256, 2) void gemm_qk_kernel() {
    extern __shared__ __align__(1024) char smem[];
    uint32_t sbase = smem_u32(smem);
    int tid  = threadIdx.x;
    int warp = tid >> 5, lane = tid & 31;
    int wm = warp & 1, wn = warp >> 1;      // warp grid 2(m) x 4(n)
    int gr = lane >> 2, tg = lane & 3;
    int m0 = blockIdx.x * GBM;
    int n0 = blockIdx.y * GBN;

    // ldmatrix lane geometry: j = lane>>3 selects the 8x8 matrix
    int j  = lane >> 3;
    int jm = j & 1;                 // +8 rows
    uint32_t kadd = (uint32_t)(j >> 1) * 16;   // +8 k-elems (bytes)
    uint32_t xorv = (uint32_t)(lane & 7) << 4; // swizzle XOR (row & 7)
    int rA[4], rB[2];
#pragma unroll
    for (int mf = 0; mf < 4; mf++) rA[mf] = wm * 64 + mf * 16 + jm * 8 + (lane & 7);
#pragma unroll
    for (int nh = 0; nh < 2; nh++) rB[nh] = wn * 32 + nh * 16 + jm * 8 + (lane & 7);

    float acc[4][4][4];
#pragma unroll
    for (int i = 0; i < 4; i++)
#pragma unroll
        for (int jj = 0; jj < 4; jj++)
#pragma unroll
            for (int q = 0; q < 4; q++) acc[i][jj][q] = 0.f;

    // prologue: stage tile 0 into buffer 0
    stage_tile(sbase, SM_AOFF(0), SM_BOFF(0), m0, n0, 0, tid);

    for (int kt = 0; kt < NKT; kt++) {
        uint32_t aoff = SM_AOFF(kt & 1);
        uint32_t boff = SM_BOFF(kt & 1);
        if (kt + 1 < NKT) {
            stage_tile(sbase, SM_AOFF((kt + 1) & 1), SM_BOFF((kt + 1) & 1),
                       m0, n0, kt + 1, tid);
            cp_wait<1>();
        } else {
            cp_wait<0>();
        }
        __syncthreads();

        uint32_t abase[4], bbase[2];
#pragma unroll
        for (int mf = 0; mf < 4; mf++) abase[mf] = sbase + aoff + rA[mf] * 128;
#pragma unroll
        for (int nh = 0; nh < 2; nh++) bbase[nh] = sbase + boff + rB[nh] * 128;

#pragma unroll
        for (int ks = 0; ks < TBK; ks += 16) {
            uint32_t cofs = ((uint32_t)(ks * 2) + kadd) ^ xorv;
            unsigned a[4][4];
#pragma unroll
            for (int mf = 0; mf < 4; mf++)
                ldsm_x4(a[mf][0], a[mf][1], a[mf][2], a[mf][3], abase[mf] + cofs);
            unsigned b[4][2];
#pragma unroll
            for (int nh = 0; nh < 2; nh++) {
                unsigned r0, r1, r2, r3;
                ldsm_x4(r0, r1, r2, r3, bbase[nh] + cofs);
                b[nh * 2][0] = r0; b[nh * 2 + 1][0] = r1;
                b[nh * 2][1] = r2; b[nh * 2 + 1][1] = r3;
            }
#pragma unroll
            for (int mf = 0; mf < 4; mf++)
#pragma unroll
                for (int nf = 0; nf < 4; nf++)
                    mma16816(acc[mf][nf], a[mf], b[nf]);
        }
        __syncthreads();   // protect buffer before next prefetch overwrites
    }

    // epilogue -> bf16
#pragma unroll
    for (int mf = 0; mf < 4; mf++) {
#pragma unroll
        for (int nf = 0; nf < 4; nf++) {
            int row = m0 + wm * 64 + mf * 16 + gr;
            int col = n0 + wn * 32 + nf * 8 + tg * 2;
            float* c = acc[mf][nf];
            *reinterpret_cast<__nv_bfloat162*>(&g_QK[(size_t)row * QKROWS + col]) =
                __floats2bfloat162_rn(c[0], c[1]);
            *reinterpret_cast<__nv_bfloat162*>(&g_QK[(size_t)(row + 8) * QKROWS + col]) =
                __floats2bfloat162_rn(c[2], c[3]);
        }
    }
}

// ---------------- attention: normalize groups, mean over slots, attn ----------------
// warp per position; lane handles memory slots m = lane and lane+32
__global__ __launch_bounds__(256) void attn_kernel(const float* __restrict__ bq,
                                                   const float* __restrict__ bk) {
    int warp = threadIdx.x >> 5, lane = threadIdx.x & 31;
    int p = blockIdx.x * 8 + warp;
    const __nv_bfloat16* qk = g_QK + (size_t)p * QKROWS;

    float qs[SQG];
#pragma unroll
    for (int jj = 0; jj < SQG; jj++) qs[jj] = 0.f;

#pragma unroll
    for (int mi = 0; mi < 2; mi++) {
        int m = lane + mi * 32;
        uint4 u0 = *reinterpret_cast<const uint4*>(qk + m * SQG);
        uint4 u1 = *reinterpret_cast<const uint4*>(qk + m * SQG + 8);
        const float4* bqv = reinterpret_cast<const float4*>(bq + m * SQG);
        float4 b0 = bqv[0], b1 = bqv[1], b2 = bqv[2], b3 = bqv[3];
        unsigned uu[8] = {u0.x, u0.y, u0.z, u0.w, u1.x, u1.y, u1.z, u1.w};
        float bb[16] = {b0.x, b0.y, b0.z, b0.w, b1.x, b1.y, b1.z, b1.w,
                        b2.x, b2.y, b2.z, b2.w, b3.x, b3.y, b3.z, b3.w};
        float qv[SQG], ss = 0.f;
#pragma unroll
        for (int h = 0; h < 8; h++) {
            __nv_bfloat162 hv = *reinterpret_cast<__nv_bfloat162*>(&uu[h]);
            float lo = __low2float(hv) + bb[2 * h];
            float hi = __high2float(hv) + bb[2 * h + 1];
            qv[2 * h] = lo; qv[2 * h + 1] = hi;
            ss += lo * lo + hi * hi;
        }
        float inv = 1.f / fmaxf(sqrtf(ss), 1e-12f);
#pragma unroll
        for (int jj = 0; jj < SQG; jj++) qs[jj] += qv[jj] * inv;
    }
#pragma unroll
    for (int off = 16; off > 0; off >>= 1)
#pragma unroll
        for (int jj = 0; jj < SQG; jj++)
            qs[jj] += __shfl_xor_sync(0xffffffffu, qs[jj], off);

#pragma unroll
    for (int mi = 0; mi < 2; mi++) {
        int m = lane + mi * 32;
        uint4 u0 = *reinterpret_cast<const uint4*>(qk + 1024 + m * SQG);
        uint4 u1 = *reinterpret_cast<const uint4*>(qk + 1024 + m * SQG + 8);
        const float4* bkv = reinterpret_cast<const float4*>(bk + m * SQG);
        float4 b0 = bkv[0], b1 = bkv[1], b2 = bkv[2], b3 = bkv[3];
        unsigned uu[8] = {u0.x, u0.y, u0.z, u0.w, u1.x, u1.y, u1.z, u1.w};
        float bb[16] = {b0.x, b0.y, b0.z, b0.w, b1.x, b1.y, b1.z, b1.w,
                        b2.x, b2.y, b2.z, b2.w, b3.x, b3.y, b3.z, b3.w};
        float ss = 0.f, dot = 0.f;
#pragma unroll
        for (int h = 0; h < 8; h++) {
            __nv_bfloat162 hv = *reinterpret_cast<__nv_bfloat162*>(&uu[h]);
            float lo = __low2float(hv) + bb[2 * h];
            float hi = __high2float(hv) + bb[2 * h + 1];
            ss += lo * lo + hi * hi;
            dot += qs[2 * h] * lo + qs[2 * h + 1] * hi;
        }
        float inv = 1.f / fmaxf(sqrtf(ss), 1e-12f);
        g_attn[(size_t)p * NMEM + m] = dot * inv * (1.f / 64.f);
    }
}

// ---------------- output: out = x + attn @ Wv + bout, written [B,256,H,W] ----------------
__global__ __launch_bounds__(256) void out_kernel(const float* __restrict__ x,
                                                  const float* __restrict__ bout,
                                                  float* __restrict__ out) {
    __shared__ float attn_s[64][65];
    __shared__ __align__(16) float wv_s[64][32];
    int p0 = blockIdx.x * 64;
    int o0 = blockIdx.y * 32;
    int tid = threadIdx.x;
    int px = tid & 63, oq = tid >> 6;

#pragma unroll
    for (int i = 0; i < 16; i++) {
        int idx = tid + i * 256;
        int pr = idx >> 6, mm = idx & 63;
        attn_s[pr][mm] = g_attn[(size_t)(p0 + pr) * NMEM + mm];
    }
#pragma unroll
    for (int i = 0; i < 8; i++) {
        int idx = tid + i * 256;
        int mm = idx >> 5, oo = idx & 31;
        wv_s[mm][oo] = g_Wv[mm * CCH + o0 + oo];
    }
    __syncthreads();

    float acc[8];
#pragma unroll
    for (int i = 0; i < 8; i++) acc[i] = 0.f;

#pragma unroll 4
    for (int m = 0; m < 64; m++) {
        float a = attn_s[px][m];
        float4 w0 = *reinterpret_cast<const float4*>(&wv_s[m][oq * 8]);
        float4 w1 = *reinterpret_cast<const float4*>(&wv_s[m][oq * 8 + 4]);
        acc[0] += a * w0.x; acc[1] += a * w0.y; acc[2] += a * w0.z; acc[3] += a * w0.w;
        acc[4] += a * w1.x; acc[5] += a * w1.y; acc[6] += a * w1.z; acc[7] += a * w1.w;
    }

    int p = p0 + px;
    int b = p >> 12, s = p & (SS - 1);
#pragma unroll
    for (int i = 0; i < 8; i++) {
        int o = o0 + oq * 8 + i;
        size_t gi = ((size_t)b * CCH + o) * SS + s;
        out[gi] = x[gi] + acc[i] + bout[o];
    }
}

// ---------------- launch ----------------
extern "C" void kernel_launch(void* const* d_in, const int* in_sizes, int n_in,
                              void* d_out, int out_size) {
    const float* x    = (const float*)d_in[0];
    const float* pos  = (const float*)d_in[1];
    const float* wq   = (const float*)d_in[2];
    const float* bq   = (const float*)d_in[3];
    const float* wk   = (const float*)d_in[4];
    const float* bk   = (const float*)d_in[5];
    const float* v    = (const float*)d_in[6];
    const float* wout = (const float*)d_in[7];
    const float* bout = (const float*)d_in[8];
    float* out = (float*)d_out;

    cudaFuncSetAttribute(gemm_qk_kernel,
                         cudaFuncAttributeMaxDynamicSharedMemorySize, SM_TOTAL);

    prep_x_kernel<<<dim3(CCH / 32, SS / 32, BB), dim3(32, 8)>>>(x);
    prep_pos_kernel<<<(MP * 64) / 256, 256>>>(pos);
    prep_w_kernel<<<(QKROWS * KPAD) / 256, 256>>>(wq, wk);
    prep_wv_kernel<<<dim3(NMEM, 4), 256>>>(v, wout);
    gemm_qk_kernel<<<dim3(MP / GBM, QKROWS / GBN), 256, SM_TOTAL>>>();
    attn_kernel<<<MP / 8, 256>>>(bq, bk);
    out_kernel<<<dim3(MP / 64, CCH / 32), 256>>>(x, bout, out);
}